// round 3
// baseline (speedup 1.0000x reference)
#include <cuda_runtime.h>

#define NN 1024
#define FF 128
#define ALPHA 0.2f
#define NEGV -9.0e15f

// Scratch (static device globals — no allocation)
__device__ float g_Wh[NN * FF];
__device__ float g_si[NN];
__device__ float g_sj[NN];
__device__ float g_att[(size_t)NN * NN];

// ---------------------------------------------------------------------------
// Kernel A: Wh = h @ W + b.  8 rows per block, 128 threads (one per out col).
// ---------------------------------------------------------------------------
__global__ __launch_bounds__(128) void k_wh(const float* __restrict__ h,
                                            const float* __restrict__ W,
                                            const float* __restrict__ b) {
    int t = threadIdx.x;
    int i0 = blockIdx.x * 8;
    __shared__ float hs[8][FF];
#pragma unroll
    for (int r = 0; r < 8; r++) hs[r][t] = h[(i0 + r) * FF + t];
    __syncthreads();
    float bb = b[t];
    float acc[8];
#pragma unroll
    for (int r = 0; r < 8; r++) acc[r] = bb;
    for (int k = 0; k < FF; k++) {
        float w = W[k * FF + t];
#pragma unroll
        for (int r = 0; r < 8; r++) acc[r] = fmaf(hs[r][k], w, acc[r]);
    }
#pragma unroll
    for (int r = 0; r < 8; r++) g_Wh[(i0 + r) * FF + t] = acc[r];
}

// ---------------------------------------------------------------------------
// Kernel S: s_i[i] = Wh[i]·a_i ; s_j[i] = Wh[i]·a_j.  One warp per row.
// ---------------------------------------------------------------------------
__global__ __launch_bounds__(32) void k_s(const float* __restrict__ aw) {
    int i = blockIdx.x;
    int lane = threadIdx.x;
    float4 wh = ((const float4*)(g_Wh + i * FF))[lane];
    float4 ai = ((const float4*)(aw))[lane];
    float4 aj = ((const float4*)(aw + FF))[lane];
    float pi = fmaf(wh.x, ai.x, fmaf(wh.y, ai.y, fmaf(wh.z, ai.z, wh.w * ai.w)));
    float pj = fmaf(wh.x, aj.x, fmaf(wh.y, aj.y, fmaf(wh.z, aj.z, wh.w * aj.w)));
#pragma unroll
    for (int o = 16; o; o >>= 1) {
        pi += __shfl_xor_sync(0xffffffffu, pi, o);
        pj += __shfl_xor_sync(0xffffffffu, pj, o);
    }
    if (lane == 0) {
        g_si[i] = pi;
        g_sj[i] = pj;
    }
}

// ---------------------------------------------------------------------------
// Kernel B (the HBM-bound one): per row i, compute
//   t[j] = e_h[i,j,:]·a_e + dlg[i,j,:]·a_d
//   e[j] = leaky_relu(s_i + s_j[j] + t[j] + a_b), mask by adj, softmax row,
// write attention row.  512 threads = 16 warps; each warp owns j % 16 cols.
// ---------------------------------------------------------------------------
__global__ __launch_bounds__(512) void k_attn(const float* __restrict__ eh,
                                              const float* __restrict__ de,
                                              const int* __restrict__ adj,
                                              const float* __restrict__ aw,
                                              const float* __restrict__ ab) {
    int i = blockIdx.x;
    int tid = threadIdx.x;
    int warp = tid >> 5, lane = tid & 31;

    __shared__ float sh[NN];
    __shared__ float red[16];

    float4 ae = ((const float4*)(aw + 2 * FF))[lane];
    float4 ad = ((const float4*)(aw + 3 * FF))[lane];
    float base = g_si[i] + ab[0];

    const float4* pe = (const float4*)(eh + (size_t)i * NN * FF);
    const float4* pd = (const float4*)(de + (size_t)i * NN * FF);

#pragma unroll 4
    for (int j = warp; j < NN; j += 16) {
        float4 x = pe[j * 32 + lane];
        float4 y = pd[j * 32 + lane];
        // fuse both dots: results are summed downstream anyway
        float p = fmaf(x.x, ae.x, fmaf(x.y, ae.y, fmaf(x.z, ae.z, x.w * ae.w)));
        p = fmaf(y.x, ad.x, fmaf(y.y, ad.y, fmaf(y.z, ad.z, fmaf(y.w, ad.w, p))));
#pragma unroll
        for (int o = 16; o; o >>= 1) p += __shfl_xor_sync(0xffffffffu, p, o);
        if (lane == 0) {
            float v = base + g_sj[j] + p;
            v = v > 0.f ? v : ALPHA * v;
            sh[j] = v;
        }
    }
    __syncthreads();

    // mask (coalesced adj read) + row max
    const int* arow = adj + (size_t)i * NN;
    float m = -3.4e38f;
    for (int j = tid; j < NN; j += 512) {
        float v = sh[j];
        if (arow[j] <= 0) v = NEGV;
        sh[j] = v;
        m = fmaxf(m, v);
    }
#pragma unroll
    for (int o = 16; o; o >>= 1) m = fmaxf(m, __shfl_xor_sync(0xffffffffu, m, o));
    if (lane == 0) red[warp] = m;
    __syncthreads();
    float mm = red[0];
#pragma unroll
    for (int k = 1; k < 16; k++) mm = fmaxf(mm, red[k]);

    // exp + row sum
    float s = 0.f;
    for (int j = tid; j < NN; j += 512) {
        float ev = __expf(sh[j] - mm);
        sh[j] = ev;
        s += ev;
    }
#pragma unroll
    for (int o = 16; o; o >>= 1) s += __shfl_xor_sync(0xffffffffu, s, o);
    __syncthreads();  // everyone done reading red[] for max before overwrite
    if (lane == 0) red[warp] = s;
    __syncthreads();
    float tot = red[0];
#pragma unroll
    for (int k = 1; k < 16; k++) tot += red[k];
    float inv = 1.f / tot;

    float* arowo = g_att + (size_t)i * NN;
    for (int j = tid; j < NN; j += 512) arowo[j] = sh[j] * inv;
}

// ---------------------------------------------------------------------------
// Kernel D: out = elu(attention @ Wh).  8 rows x 128 cols per block.
// ---------------------------------------------------------------------------
__global__ __launch_bounds__(128) void k_out(float* __restrict__ out) {
    int t = threadIdx.x;
    int i0 = blockIdx.x * 8;
    __shared__ float as_[8][64];
    float acc[8];
#pragma unroll
    for (int r = 0; r < 8; r++) acc[r] = 0.f;

    for (int jb = 0; jb < NN; jb += 64) {
        __syncthreads();
#pragma unroll
        for (int q = 0; q < 4; q++) {
            int idx = q * 128 + t;           // 0..511
            int r = idx >> 6, c = idx & 63;
            as_[r][c] = g_att[(size_t)(i0 + r) * NN + jb + c];
        }
        __syncthreads();
#pragma unroll 8
        for (int jj = 0; jj < 64; jj++) {
            float w = g_Wh[(jb + jj) * FF + t];
#pragma unroll
            for (int r = 0; r < 8; r++) acc[r] = fmaf(as_[r][jj], w, acc[r]);
        }
    }
#pragma unroll
    for (int r = 0; r < 8; r++) {
        float v = acc[r];
        out[(i0 + r) * FF + t] = v > 0.f ? v : expm1f(v);
    }
}

// ---------------------------------------------------------------------------
// Launch.  Input order per metadata: h, e_h, dialogue_embedding, adj, W_w,
// W_b, a_w, a_b.  Output: fp32 [1024, 128].
// ---------------------------------------------------------------------------
extern "C" void kernel_launch(void* const* d_in, const int* in_sizes, int n_in,
                              void* d_out, int out_size) {
    const float* h   = (const float*)d_in[0];
    const float* eh  = (const float*)d_in[1];
    const float* de  = (const float*)d_in[2];
    const int*   adj = (const int*)d_in[3];
    const float* Ww  = (const float*)d_in[4];
    const float* Wb  = (const float*)d_in[5];
    const float* aw  = (const float*)d_in[6];
    const float* ab  = (const float*)d_in[7];
    float* out = (float*)d_out;

    k_wh<<<NN / 8, 128>>>(h, Ww, Wb);
    k_s<<<NN, 32>>>(aw);
    k_attn<<<NN, 512>>>(eh, de, adj, aw, ab);
    k_out<<<NN / 8, 128>>>(out);
}

// round 5
// speedup vs baseline: 1.3573x; 1.3573x over previous
#include <cuda_runtime.h>

#define NN 1024
#define FF 128
#define ALPHA 0.2f
#define NEGV -9.0e15f

// Scratch (static device globals — no allocation)
__device__ float g_Wh[NN * FF];
__device__ float g_si[NN];
__device__ float g_sj[NN];
__device__ float g_att[(size_t)NN * NN];

__device__ __forceinline__ float4 ldcs4(const float4* p) {
#if __CUDA_ARCH__ >= 800
    float4 v;
    asm volatile("ld.global.cs.v4.f32 {%0,%1,%2,%3}, [%4];"
                 : "=f"(v.x), "=f"(v.y), "=f"(v.z), "=f"(v.w) : "l"(p));
    return v;
#else
    return *p;
#endif
}

// ---------------------------------------------------------------------------
// Kernel A: Wh = h @ W + b, fused with s_i = Wh·a_i, s_j = Wh·a_j.
// 8 rows per block, 128 threads (one per out col).
// ---------------------------------------------------------------------------
__global__ __launch_bounds__(128) void k_wh(const float* __restrict__ h,
                                            const float* __restrict__ W,
                                            const float* __restrict__ b,
                                            const float* __restrict__ aw) {
    int t = threadIdx.x;
    int warp = t >> 5, lane = t & 31;
    int i0 = blockIdx.x * 8;
    __shared__ float hs[8][FF];
    __shared__ float redi[8][4], redj[8][4];
#pragma unroll
    for (int r = 0; r < 8; r++) hs[r][t] = h[(i0 + r) * FF + t];
    __syncthreads();
    float bb = b[t];
    float acc[8];
#pragma unroll
    for (int r = 0; r < 8; r++) acc[r] = bb;
    for (int k = 0; k < FF; k++) {
        float w = W[k * FF + t];
#pragma unroll
        for (int r = 0; r < 8; r++) acc[r] = fmaf(hs[r][k], w, acc[r]);
    }
    float ai = aw[t], aj = aw[FF + t];
#pragma unroll
    for (int r = 0; r < 8; r++) {
        g_Wh[(i0 + r) * FF + t] = acc[r];
        float pi = acc[r] * ai;
        float pj = acc[r] * aj;
#pragma unroll
        for (int o = 16; o; o >>= 1) {
            pi += __shfl_xor_sync(0xffffffffu, pi, o);
            pj += __shfl_xor_sync(0xffffffffu, pj, o);
        }
        if (lane == 0) { redi[r][warp] = pi; redj[r][warp] = pj; }
    }
    __syncthreads();
    if (t < 8)
        g_si[i0 + t] = redi[t][0] + redi[t][1] + redi[t][2] + redi[t][3];
    else if (t < 16) {
        int r = t - 8;
        g_sj[i0 + r] = redj[r][0] + redj[r][1] + redj[r][2] + redj[r][3];
    }
}

// ---------------------------------------------------------------------------
// Kernel B (HBM-bound): per row i, fused dual GEMV over e_h/dialogue +
// leaky-ReLU + adj mask + row softmax.  256 threads (8 warps) per block ->
// 8 blocks/SM -> all 1024 blocks resident in ONE wave.
// ---------------------------------------------------------------------------
__global__ __launch_bounds__(256) void k_attn(const float* __restrict__ eh,
                                              const float* __restrict__ de,
                                              const int* __restrict__ adj,
                                              const float* __restrict__ aw,
                                              const float* __restrict__ ab) {
    int i = blockIdx.x;
    int tid = threadIdx.x;
    int warp = tid >> 5, lane = tid & 31;

    __shared__ float sh[NN];
    __shared__ float red[8];

    float4 ae = ((const float4*)(aw + 2 * FF))[lane];
    float4 ad = ((const float4*)(aw + 3 * FF))[lane];
    float base = g_si[i] + ab[0];

    const float4* pe = (const float4*)(eh + (size_t)i * NN * FF);
    const float4* pd = (const float4*)(de + (size_t)i * NN * FF);

#pragma unroll 4
    for (int j = warp; j < NN; j += 8) {
        float4 x = ldcs4(pe + j * 32 + lane);
        float4 y = ldcs4(pd + j * 32 + lane);
        // fuse both dots: results are summed downstream anyway
        float p = fmaf(x.x, ae.x, fmaf(x.y, ae.y, fmaf(x.z, ae.z, x.w * ae.w)));
        p = fmaf(y.x, ad.x, fmaf(y.y, ad.y, fmaf(y.z, ad.z, fmaf(y.w, ad.w, p))));
#pragma unroll
        for (int o = 16; o; o >>= 1) p += __shfl_xor_sync(0xffffffffu, p, o);
        if (lane == 0) {
            float v = base + g_sj[j] + p;
            v = v > 0.f ? v : ALPHA * v;
            sh[j] = v;
        }
    }
    __syncthreads();

    // mask (coalesced adj read) + row max
    const int* arow = adj + (size_t)i * NN;
    float m = -3.4e38f;
    for (int j = tid; j < NN; j += 256) {
        float v = sh[j];
        if (arow[j] <= 0) v = NEGV;
        sh[j] = v;
        m = fmaxf(m, v);
    }
#pragma unroll
    for (int o = 16; o; o >>= 1) m = fmaxf(m, __shfl_xor_sync(0xffffffffu, m, o));
    if (lane == 0) red[warp] = m;
    __syncthreads();
    float mm = red[0];
#pragma unroll
    for (int k = 1; k < 8; k++) mm = fmaxf(mm, red[k]);

    // exp + row sum
    float s = 0.f;
    for (int j = tid; j < NN; j += 256) {
        float ev = __expf(sh[j] - mm);
        sh[j] = ev;
        s += ev;
    }
#pragma unroll
    for (int o = 16; o; o >>= 1) s += __shfl_xor_sync(0xffffffffu, s, o);
    __syncthreads();  // everyone done reading red[] (max) before overwrite
    if (lane == 0) red[warp] = s;
    __syncthreads();
    float tot = red[0];
#pragma unroll
    for (int k = 1; k < 8; k++) tot += red[k];
    float inv = 1.f / tot;

    float* arowo = g_att + (size_t)i * NN;
    for (int j = tid; j < NN; j += 256) arowo[j] = sh[j] * inv;
}

// ---------------------------------------------------------------------------
// Kernel D: out = elu(attention @ Wh).  128 blocks x 512 threads.
// thread = (colquad c in [0,32), row r in [0,8), khalf in {0,1}).
// Per iter: 1 float4 att (uniform across warp) + 4 float4 Wh (coalesced),
// 16 FMAs. K-split halves reduced via smem; ELU fused at store.
// ---------------------------------------------------------------------------
__global__ __launch_bounds__(512) void k_out(float* __restrict__ out) {
    int tid = threadIdx.x;
    int c = tid & 31;          // col quad -> cols [4c, 4c+4)
    int r = (tid >> 5) & 7;    // row within block
    int kh = tid >> 8;         // k half
    int i = blockIdx.x * 8 + r;

    const float4* whp = (const float4*)g_Wh;  // [1024][32] float4
    const float4* ap = (const float4*)(g_att + (size_t)i * NN + kh * 512);

    float4 acc = make_float4(0.f, 0.f, 0.f, 0.f);
    int kbase = kh * 512;
#pragma unroll 2
    for (int k = 0; k < 512; k += 4) {
        float4 a4 = ap[k >> 2];
        float4 w0 = whp[(kbase + k + 0) * 32 + c];
        float4 w1 = whp[(kbase + k + 1) * 32 + c];
        float4 w2 = whp[(kbase + k + 2) * 32 + c];
        float4 w3 = whp[(kbase + k + 3) * 32 + c];
        acc.x = fmaf(a4.x, w0.x, acc.x); acc.y = fmaf(a4.x, w0.y, acc.y);
        acc.z = fmaf(a4.x, w0.z, acc.z); acc.w = fmaf(a4.x, w0.w, acc.w);
        acc.x = fmaf(a4.y, w1.x, acc.x); acc.y = fmaf(a4.y, w1.y, acc.y);
        acc.z = fmaf(a4.y, w1.z, acc.z); acc.w = fmaf(a4.y, w1.w, acc.w);
        acc.x = fmaf(a4.z, w2.x, acc.x); acc.y = fmaf(a4.z, w2.y, acc.y);
        acc.z = fmaf(a4.z, w2.z, acc.z); acc.w = fmaf(a4.z, w2.w, acc.w);
        acc.x = fmaf(a4.w, w3.x, acc.x); acc.y = fmaf(a4.w, w3.y, acc.y);
        acc.z = fmaf(a4.w, w3.z, acc.z); acc.w = fmaf(a4.w, w3.w, acc.w);
    }

    __shared__ float4 sred[8][32];
    if (kh == 1) sred[r][c] = acc;
    __syncthreads();
    if (kh == 0) {
        float4 o = sred[r][c];
        acc.x += o.x; acc.y += o.y; acc.z += o.z; acc.w += o.w;
        float4 res;
        res.x = acc.x > 0.f ? acc.x : expm1f(acc.x);
        res.y = acc.y > 0.f ? acc.y : expm1f(acc.y);
        res.z = acc.z > 0.f ? acc.z : expm1f(acc.z);
        res.w = acc.w > 0.f ? acc.w : expm1f(acc.w);
        ((float4*)(out + (size_t)i * FF))[c] = res;
    }
}

// ---------------------------------------------------------------------------
// Launch.  Inputs: h, e_h, dialogue_embedding, adj, W_w, W_b, a_w, a_b.
// Output: fp32 [1024, 128].
// ---------------------------------------------------------------------------
extern "C" void kernel_launch(void* const* d_in, const int* in_sizes, int n_in,
                              void* d_out, int out_size) {
    const float* h   = (const float*)d_in[0];
    const float* eh  = (const float*)d_in[1];
    const float* de  = (const float*)d_in[2];
    const int*   adj = (const int*)d_in[3];
    const float* Ww  = (const float*)d_in[4];
    const float* Wb  = (const float*)d_in[5];
    const float* aw  = (const float*)d_in[6];
    const float* ab  = (const float*)d_in[7];
    float* out = (float*)d_out;

    k_wh<<<NN / 8, 128>>>(h, Ww, Wb, aw);
    k_attn<<<NN, 256>>>(eh, de, adj, aw, ab);
    k_out<<<NN / 8, 512>>>(out);
}

// round 6
// speedup vs baseline: 1.4085x; 1.0378x over previous
#include <cuda_runtime.h>

#define NN 1024
#define FF 128
#define ALPHA 0.2f
#define NEGV -9.0e15f

// Scratch (static device globals — no allocation)
__device__ float g_Wh[NN * FF];
__device__ float g_si[NN];
__device__ float g_sj[NN];
__device__ float g_att[(size_t)NN * NN];

__device__ __forceinline__ float4 ldcs4(const float4* p) {
#if __CUDA_ARCH__ >= 800
    float4 v;
    asm volatile("ld.global.cs.v4.f32 {%0,%1,%2,%3}, [%4];"
                 : "=f"(v.x), "=f"(v.y), "=f"(v.z), "=f"(v.w) : "l"(p));
    return v;
#else
    return *p;
#endif
}

// ---------------------------------------------------------------------------
// Kernel A: Wh = h @ W + b, fused with s_i = Wh·a_i, s_j = Wh·a_j.
// ONE row per block, 1024 blocks x 128 threads -> ~28 warps/SM, W is
// L2-resident (64 KB) after the first wave.
// ---------------------------------------------------------------------------
__global__ __launch_bounds__(128) void k_wh(const float* __restrict__ h,
                                            const float* __restrict__ W,
                                            const float* __restrict__ b,
                                            const float* __restrict__ aw) {
    int t = threadIdx.x;
    int warp = t >> 5, lane = t & 31;
    int i = blockIdx.x;
    __shared__ float hs[FF];
    __shared__ float red[2][4];
    hs[t] = h[i * FF + t];
    __syncthreads();
    float acc = b[t];
#pragma unroll 8
    for (int k = 0; k < FF; k++) acc = fmaf(hs[k], W[k * FF + t], acc);
    g_Wh[i * FF + t] = acc;
    float pi = acc * aw[t];
    float pj = acc * aw[FF + t];
#pragma unroll
    for (int o = 16; o; o >>= 1) {
        pi += __shfl_xor_sync(0xffffffffu, pi, o);
        pj += __shfl_xor_sync(0xffffffffu, pj, o);
    }
    if (lane == 0) { red[0][warp] = pi; red[1][warp] = pj; }
    __syncthreads();
    if (t == 0)  g_si[i] = red[0][0] + red[0][1] + red[0][2] + red[0][3];
    if (t == 32) g_sj[i] = red[1][0] + red[1][1] + red[1][2] + red[1][3];
}

// ---------------------------------------------------------------------------
// Kernel B (HBM-bound, ~79% of spec already): per row i, fused dual GEMV
// over e_h/dialogue + leaky-ReLU + adj mask + row softmax.  256 threads,
// 8 blocks/SM -> all 1024 blocks resident in ONE wave.  UNCHANGED.
// ---------------------------------------------------------------------------
__global__ __launch_bounds__(256) void k_attn(const float* __restrict__ eh,
                                              const float* __restrict__ de,
                                              const int* __restrict__ adj,
                                              const float* __restrict__ aw,
                                              const float* __restrict__ ab) {
    int i = blockIdx.x;
    int tid = threadIdx.x;
    int warp = tid >> 5, lane = tid & 31;

    __shared__ float sh[NN];
    __shared__ float red[8];

    float4 ae = ((const float4*)(aw + 2 * FF))[lane];
    float4 ad = ((const float4*)(aw + 3 * FF))[lane];
    float base = g_si[i] + ab[0];

    const float4* pe = (const float4*)(eh + (size_t)i * NN * FF);
    const float4* pd = (const float4*)(de + (size_t)i * NN * FF);

#pragma unroll 4
    for (int j = warp; j < NN; j += 8) {
        float4 x = ldcs4(pe + j * 32 + lane);
        float4 y = ldcs4(pd + j * 32 + lane);
        float p = fmaf(x.x, ae.x, fmaf(x.y, ae.y, fmaf(x.z, ae.z, x.w * ae.w)));
        p = fmaf(y.x, ad.x, fmaf(y.y, ad.y, fmaf(y.z, ad.z, fmaf(y.w, ad.w, p))));
#pragma unroll
        for (int o = 16; o; o >>= 1) p += __shfl_xor_sync(0xffffffffu, p, o);
        if (lane == 0) {
            float v = base + g_sj[j] + p;
            v = v > 0.f ? v : ALPHA * v;
            sh[j] = v;
        }
    }
    __syncthreads();

    const int* arow = adj + (size_t)i * NN;
    float m = -3.4e38f;
    for (int j = tid; j < NN; j += 256) {
        float v = sh[j];
        if (arow[j] <= 0) v = NEGV;
        sh[j] = v;
        m = fmaxf(m, v);
    }
#pragma unroll
    for (int o = 16; o; o >>= 1) m = fmaxf(m, __shfl_xor_sync(0xffffffffu, m, o));
    if (lane == 0) red[warp] = m;
    __syncthreads();
    float mm = red[0];
#pragma unroll
    for (int k = 1; k < 8; k++) mm = fmaxf(mm, red[k]);

    float s = 0.f;
    for (int j = tid; j < NN; j += 256) {
        float ev = __expf(sh[j] - mm);
        sh[j] = ev;
        s += ev;
    }
#pragma unroll
    for (int o = 16; o; o >>= 1) s += __shfl_xor_sync(0xffffffffu, s, o);
    __syncthreads();
    if (lane == 0) red[warp] = s;
    __syncthreads();
    float tot = red[0];
#pragma unroll
    for (int k = 1; k < 8; k++) tot += red[k];
    float inv = 1.f / tot;

    float* arowo = g_att + (size_t)i * NN;
    for (int j = tid; j < NN; j += 256) arowo[j] = sh[j] * inv;
}

// ---------------------------------------------------------------------------
// Kernel D: out = elu(attention @ Wh).  SMEM-TILED GEMM.
// 256 blocks x 256 threads.  Block = 4 rows x 128 cols, 2-way k-split.
// thread = (c4 in [0,32), rr in [0,4), kh in {0,1}).
// Wh staged in smem in 32-k-row tiles (each kh group has its own tile for
// its k half).  Global Wh traffic: 512 KB/block (vs 4 MB before).
// ---------------------------------------------------------------------------
__global__ __launch_bounds__(256) void k_out(float* __restrict__ out) {
    int tid = threadIdx.x;
    int c4 = tid & 31;          // col quad -> cols [4*c4, 4*c4+4)
    int rr = (tid >> 5) & 3;    // row within block
    int kh = tid >> 7;          // k half: [kh*512, kh*512+512)
    int ltid = tid & 127;       // id within kh group
    int i0 = blockIdx.x * 4;

    __shared__ float whs[2][32][FF];   // 32 KB: per-kh-group Wh k-tile
    __shared__ float as_[2][4][32];    // att tiles
    __shared__ float4 sred[4][32];     // kh combine

    const float4* wh4 = (const float4*)g_Wh;
    int kbase = kh * 512;

    float4 acc = make_float4(0.f, 0.f, 0.f, 0.f);

    for (int kb = 0; kb < 512; kb += 32) {
        __syncthreads();
        // Wh tile: 32 k-rows x 128 cols = 1024 float4 per group, 8/thread.
#pragma unroll
        for (int q = 0; q < 8; q++) {
            int idx = q * 128 + ltid;        // 0..1023
            int kr = idx >> 5, cc = idx & 31;
            *((float4*)&whs[kh][kr][cc * 4]) =
                wh4[(size_t)(kbase + kb + kr) * 32 + cc];
        }
        // att tile: 4 rows x 32 k = 128 floats per group, 1/thread.
        {
            int r = ltid >> 5, kk = ltid & 31;
            as_[kh][r][kk] = g_att[(size_t)(i0 + r) * NN + kbase + kb + kk];
        }
        __syncthreads();
#pragma unroll
        for (int kk = 0; kk < 32; kk++) {
            float a = as_[kh][rr][kk];                       // broadcast LDS
            float4 w = *((const float4*)&whs[kh][kk][c4 * 4]);  // LDS.128
            acc.x = fmaf(a, w.x, acc.x);
            acc.y = fmaf(a, w.y, acc.y);
            acc.z = fmaf(a, w.z, acc.z);
            acc.w = fmaf(a, w.w, acc.w);
        }
    }

    if (kh == 1) sred[rr][c4] = acc;
    __syncthreads();
    if (kh == 0) {
        float4 o = sred[rr][c4];
        acc.x += o.x; acc.y += o.y; acc.z += o.z; acc.w += o.w;
        float4 res;
        res.x = acc.x > 0.f ? acc.x : expm1f(acc.x);
        res.y = acc.y > 0.f ? acc.y : expm1f(acc.y);
        res.z = acc.z > 0.f ? acc.z : expm1f(acc.z);
        res.w = acc.w > 0.f ? acc.w : expm1f(acc.w);
        ((float4*)(out + (size_t)(i0 + rr) * FF))[c4] = res;
    }
}

// ---------------------------------------------------------------------------
// Launch.  Inputs: h, e_h, dialogue_embedding, adj, W_w, W_b, a_w, a_b.
// Output: fp32 [1024, 128].
// ---------------------------------------------------------------------------
extern "C" void kernel_launch(void* const* d_in, const int* in_sizes, int n_in,
                              void* d_out, int out_size) {
    const float* h   = (const float*)d_in[0];
    const float* eh  = (const float*)d_in[1];
    const float* de  = (const float*)d_in[2];
    const int*   adj = (const int*)d_in[3];
    const float* Ww  = (const float*)d_in[4];
    const float* Wb  = (const float*)d_in[5];
    const float* aw  = (const float*)d_in[6];
    const float* ab  = (const float*)d_in[7];
    float* out = (float*)d_out;

    k_wh<<<NN, 128>>>(h, Ww, Wb, aw);
    k_attn<<<NN, 256>>>(eh, de, adj, aw, ab);
    k_out<<<NN / 4, 256>>>(out);
}

// round 9
// speedup vs baseline: 1.5946x; 1.1321x over previous
#include <cuda_runtime.h>

#define NN 1024
#define FF 128
#define ALPHA 0.2f
#define NEGV -9.0e15f

// Scratch (static device globals — no allocation)
__device__ float g_Wh[NN * FF];
__device__ float g_si[NN];
__device__ float g_sj[NN];
__device__ float g_inv[NN];
__device__ float g_att[(size_t)NN * NN];   // UNNORMALIZED exp weights

__device__ __forceinline__ float4 ldcs4(const float4* p) {
#if __CUDA_ARCH__ >= 800
    float4 v;
    asm volatile("ld.global.cs.v4.f32 {%0,%1,%2,%3}, [%4];"
                 : "=f"(v.x), "=f"(v.y), "=f"(v.z), "=f"(v.w) : "l"(p));
    return v;
#else
    return *p;
#endif
}

// ---------------------------------------------------------------------------
// Kernel A: Wh = h @ W + b, fused s_i/s_j.  2 rows/block, 512 blocks x 128.
// Each W element load feeds 2 FMAs -> 32 MB L2 traffic total.
// ---------------------------------------------------------------------------
__global__ __launch_bounds__(128) void k_wh(const float* __restrict__ h,
                                            const float* __restrict__ W,
                                            const float* __restrict__ b,
                                            const float* __restrict__ aw) {
    int t = threadIdx.x;
    int warp = t >> 5, lane = t & 31;
    int i0 = blockIdx.x * 2;
    __shared__ float hs[2][FF];
    __shared__ float red[2][2][4];   // [row][i/j][warp]
    hs[0][t] = h[i0 * FF + t];
    hs[1][t] = h[(i0 + 1) * FF + t];
    __syncthreads();
    float bb = b[t];
    float a0 = bb, a1 = bb;
#pragma unroll 8
    for (int k = 0; k < FF; k++) {
        float w = W[k * FF + t];
        a0 = fmaf(hs[0][k], w, a0);
        a1 = fmaf(hs[1][k], w, a1);
    }
    g_Wh[i0 * FF + t] = a0;
    g_Wh[(i0 + 1) * FF + t] = a1;
    float ai = aw[t], aj = aw[FF + t];
    float p0 = a0 * ai, p1 = a0 * aj, p2 = a1 * ai, p3 = a1 * aj;
#pragma unroll
    for (int o = 16; o; o >>= 1) {
        p0 += __shfl_xor_sync(0xffffffffu, p0, o);
        p1 += __shfl_xor_sync(0xffffffffu, p1, o);
        p2 += __shfl_xor_sync(0xffffffffu, p2, o);
        p3 += __shfl_xor_sync(0xffffffffu, p3, o);
    }
    if (lane == 0) {
        red[0][0][warp] = p0; red[0][1][warp] = p1;
        red[1][0][warp] = p2; red[1][1][warp] = p3;
    }
    __syncthreads();
    if (t < 2) {
        g_si[i0 + t] = red[t][0][0] + red[t][0][1] + red[t][0][2] + red[t][0][3];
        g_sj[i0 + t] = red[t][1][0] + red[t][1][1] + red[t][1][2] + red[t][1][3];
    }
}

// ---------------------------------------------------------------------------
// Kernel B (HBM-bound): per row i, fused dual GEMV + leaky-ReLU + mask +
// softmax (unnormalized store + g_inv).  __launch_bounds__(256,7) caps regs
// at 36 so 7 blocks/SM are resident -> ALL 1024 blocks in ONE wave.
// ---------------------------------------------------------------------------
__global__ __launch_bounds__(256, 7) void k_attn(const float* __restrict__ eh,
                                                 const float* __restrict__ de,
                                                 const int* __restrict__ adj,
                                                 const float* __restrict__ aw,
                                                 const float* __restrict__ ab) {
    int i = blockIdx.x;
    int tid = threadIdx.x;
    int warp = tid >> 5, lane = tid & 31;

    __shared__ float sh[NN];
    __shared__ float red[8];

    float4 ae = ((const float4*)(aw + 2 * FF))[lane];
    float4 ad = ((const float4*)(aw + 3 * FF))[lane];
    float base = g_si[i] + ab[0];

    const float4* pe = (const float4*)(eh + (size_t)i * NN * FF);
    const float4* pd = (const float4*)(de + (size_t)i * NN * FF);

    // Stream 1 MB (e_h row-block + dialogue row-block); fused dual dot.
#pragma unroll 2
    for (int j = warp; j < NN; j += 8) {
        float4 x = ldcs4(pe + j * 32 + lane);
        float4 y = ldcs4(pd + j * 32 + lane);
        float p = fmaf(x.x, ae.x, fmaf(x.y, ae.y, fmaf(x.z, ae.z, x.w * ae.w)));
        p = fmaf(y.x, ad.x, fmaf(y.y, ad.y, fmaf(y.z, ad.z, fmaf(y.w, ad.w, p))));
#pragma unroll
        for (int o = 16; o; o >>= 1) p += __shfl_xor_sync(0xffffffffu, p, o);
        if (lane == 0) {
            float v = base + g_sj[j] + p;
            sh[j] = v > 0.f ? v : ALPHA * v;
        }
    }
    __syncthreads();

    // Mask + max: each thread owns exactly 4 j's (stay in registers after).
    int4 a4 = ((const int4*)(adj + (size_t)i * NN))[tid];
    float4 v4 = *((float4*)&sh[tid * 4]);
    v4.x = a4.x > 0 ? v4.x : NEGV;
    v4.y = a4.y > 0 ? v4.y : NEGV;
    v4.z = a4.z > 0 ? v4.z : NEGV;
    v4.w = a4.w > 0 ? v4.w : NEGV;
    float m = fmaxf(fmaxf(v4.x, v4.y), fmaxf(v4.z, v4.w));
#pragma unroll
    for (int o = 16; o; o >>= 1) m = fmaxf(m, __shfl_xor_sync(0xffffffffu, m, o));
    if (lane == 0) red[warp] = m;
    __syncthreads();
    float mm = red[0];
#pragma unroll
    for (int k = 1; k < 8; k++) mm = fmaxf(mm, red[k]);

    // exp + sum; store UNNORMALIZED weights; inv goes to g_inv.
    float4 e4;
    e4.x = __expf(v4.x - mm);
    e4.y = __expf(v4.y - mm);
    e4.z = __expf(v4.z - mm);
    e4.w = __expf(v4.w - mm);
    ((float4*)(g_att + (size_t)i * NN))[tid] = e4;
    float s = (e4.x + e4.y) + (e4.z + e4.w);
#pragma unroll
    for (int o = 16; o; o >>= 1) s += __shfl_xor_sync(0xffffffffu, s, o);
    __syncthreads();              // red[] (max) fully consumed before reuse
    if (lane == 0) red[warp] = s;
    __syncthreads();
    if (tid == 0) {
        float tot = red[0];
#pragma unroll
        for (int k = 1; k < 8; k++) tot += red[k];
        g_inv[i] = 1.f / tot;
    }
}

// ---------------------------------------------------------------------------
// Kernel D: out = elu((att*inv) @ Wh).  256 blocks x 256 threads, 4 rows.
// Attention rows staged TRANSPOSED in smem (inv folded in), inner loop =
// 1 broadcast LDS.128 + 1 coalesced LDG.128 + 16 FMA per j.
// Wh L2 traffic: 512 KB/block -> 128 MB total.
// ---------------------------------------------------------------------------
__global__ __launch_bounds__(256) void k_out(float* __restrict__ out) {
    int tid = threadIdx.x;
    int warp = tid >> 5, lane = tid & 31;
    int i0 = blockIdx.x * 4;

    __shared__ float4 attT[NN];        // attT[j] = {row0..row3} * inv  (16 KB)
    __shared__ float4 sred[4][8][32];  // cross-warp reduce              (16 KB)

    float iv0 = g_inv[i0 + 0], iv1 = g_inv[i0 + 1];
    float iv2 = g_inv[i0 + 2], iv3 = g_inv[i0 + 3];
    const float* att0 = g_att + (size_t)(i0 + 0) * NN;
    const float* att1 = g_att + (size_t)(i0 + 1) * NN;
    const float* att2 = g_att + (size_t)(i0 + 2) * NN;
    const float* att3 = g_att + (size_t)(i0 + 3) * NN;
#pragma unroll
    for (int q = 0; q < 4; q++) {
        int j = tid + q * 256;
        float4 v;
        v.x = att0[j] * iv0;
        v.y = att1[j] * iv1;
        v.z = att2[j] * iv2;
        v.w = att3[j] * iv3;
        attT[j] = v;                   // STS.128, lanes consecutive -> no conflict
    }
    __syncthreads();

    float4 c0 = make_float4(0.f, 0.f, 0.f, 0.f);
    float4 c1 = c0, c2 = c0, c3 = c0;
    const float4* wh4 = (const float4*)g_Wh;
    int jb = warp * 128;
#pragma unroll 4
    for (int jj = 0; jj < 128; jj++) {
        float4 a = attT[jb + jj];                       // broadcast
        float4 w = wh4[(size_t)(jb + jj) * 32 + lane];  // coalesced 512B/warp
        c0.x = fmaf(a.x, w.x, c0.x); c0.y = fmaf(a.x, w.y, c0.y);
        c0.z = fmaf(a.x, w.z, c0.z); c0.w = fmaf(a.x, w.w, c0.w);
        c1.x = fmaf(a.y, w.x, c1.x); c1.y = fmaf(a.y, w.y, c1.y);
        c1.z = fmaf(a.y, w.z, c1.z); c1.w = fmaf(a.y, w.w, c1.w);
        c2.x = fmaf(a.z, w.x, c2.x); c2.y = fmaf(a.z, w.y, c2.y);
        c2.z = fmaf(a.z, w.z, c2.z); c2.w = fmaf(a.z, w.w, c2.w);
        c3.x = fmaf(a.w, w.x, c3.x); c3.y = fmaf(a.w, w.y, c3.y);
        c3.z = fmaf(a.w, w.z, c3.z); c3.w = fmaf(a.w, w.w, c3.w);
    }
    sred[0][warp][lane] = c0;
    sred[1][warp][lane] = c1;
    sred[2][warp][lane] = c2;
    sred[3][warp][lane] = c3;
    __syncthreads();

    if (tid < 128) {
        int r = tid >> 5, c = tid & 31;
        float4 s = sred[r][0][c];
#pragma unroll
        for (int w = 1; w < 8; w++) {
            float4 o = sred[r][w][c];
            s.x += o.x; s.y += o.y; s.z += o.z; s.w += o.w;
        }
        float4 res;
        res.x = s.x > 0.f ? s.x : expm1f(s.x);
        res.y = s.y > 0.f ? s.y : expm1f(s.y);
        res.z = s.z > 0.f ? s.z : expm1f(s.z);
        res.w = s.w > 0.f ? s.w : expm1f(s.w);
        ((float4*)(out + (size_t)(i0 + r) * FF))[c] = res;
    }
}

// ---------------------------------------------------------------------------
// Launch.  Inputs: h, e_h, dialogue_embedding, adj, W_w, W_b, a_w, a_b.
// Output: fp32 [1024, 128].
// ---------------------------------------------------------------------------
extern "C" void kernel_launch(void* const* d_in, const int* in_sizes, int n_in,
                              void* d_out, int out_size) {
    const float* h   = (const float*)d_in[0];
    const float* eh  = (const float*)d_in[1];
    const float* de  = (const float*)d_in[2];
    const int*   adj = (const int*)d_in[3];
    const float* Ww  = (const float*)d_in[4];
    const float* Wb  = (const float*)d_in[5];
    const float* aw  = (const float*)d_in[6];
    const float* ab  = (const float*)d_in[7];
    float* out = (float*)d_out;

    k_wh<<<NN / 2, 128>>>(h, Ww, Wb, aw);
    k_attn<<<NN, 256>>>(eh, de, adj, aw, ab);
    k_out<<<NN / 4, 256>>>(out);
}

// round 10
// speedup vs baseline: 1.7519x; 1.0987x over previous
#include <cuda_runtime.h>

#define NN 1024
#define FF 128
#define ALPHA 0.2f
#define NEGV -9.0e15f

// Scratch (static device globals — no allocation)
__device__ float g_Wh[NN * FF];
__device__ float g_si[NN];
__device__ float g_sj[NN];
__device__ float g_inv[NN];
__device__ float g_att[(size_t)NN * NN];   // UNNORMALIZED exp weights

__device__ __forceinline__ float4 ldcs4(const float4* p) {
#if __CUDA_ARCH__ >= 800
    float4 v;
    asm volatile("ld.global.cs.v4.f32 {%0,%1,%2,%3}, [%4];"
                 : "=f"(v.x), "=f"(v.y), "=f"(v.z), "=f"(v.w) : "l"(p));
    return v;
#else
    return *p;
#endif
}

// ---------------------------------------------------------------------------
// Kernel A (v3): Wh = h @ W + b, fused s_i/s_j.  1 row/block, 1024 blocks x
// 128 threads.  K-SPLIT: warp w owns k in [32w, 32w+32); lane owns col quad
// [4*lane, 4*lane+4).  Per thread: 32 x (LDS broadcast + LDG.128 + 4 FMA)
// -> 4x fewer load issues/waits than the scalar version; wide grid for
// latency hiding (7 blocks/SM).
// ---------------------------------------------------------------------------
__global__ __launch_bounds__(128) void k_wh(const float* __restrict__ h,
                                            const float* __restrict__ W,
                                            const float* __restrict__ b,
                                            const float* __restrict__ aw) {
    int t = threadIdx.x;
    int warp = t >> 5, lane = t & 31;
    int i = blockIdx.x;
    __shared__ float hs[FF];
    __shared__ float4 part[4][32];     // [kgroup][colquad]
    hs[t] = h[i * FF + t];
    __syncthreads();

    const float4* W4 = (const float4*)W;   // [128][32] float4
    float4 acc = make_float4(0.f, 0.f, 0.f, 0.f);
    int k0 = warp * 32;
#pragma unroll 8
    for (int kk = 0; kk < 32; kk++) {
        float hv = hs[k0 + kk];
        float4 w = W4[(k0 + kk) * 32 + lane];   // coalesced 512B/warp
        acc.x = fmaf(hv, w.x, acc.x);
        acc.y = fmaf(hv, w.y, acc.y);
        acc.z = fmaf(hv, w.z, acc.z);
        acc.w = fmaf(hv, w.w, acc.w);
    }
    part[warp][lane] = acc;
    __syncthreads();

    if (warp == 0) {
        float4 s = part[0][lane];
        float4 p1 = part[1][lane], p2 = part[2][lane], p3 = part[3][lane];
        float4 bb = ((const float4*)b)[lane];
        s.x += p1.x + p2.x + p3.x + bb.x;
        s.y += p1.y + p2.y + p3.y + bb.y;
        s.z += p1.z + p2.z + p3.z + bb.z;
        s.w += p1.w + p2.w + p3.w + bb.w;
        ((float4*)(g_Wh + i * FF))[lane] = s;

        float4 ai = ((const float4*)aw)[lane];
        float4 aj = ((const float4*)(aw + FF))[lane];
        float pi = fmaf(s.x, ai.x, fmaf(s.y, ai.y, fmaf(s.z, ai.z, s.w * ai.w)));
        float pj = fmaf(s.x, aj.x, fmaf(s.y, aj.y, fmaf(s.z, aj.z, s.w * aj.w)));
#pragma unroll
        for (int o = 16; o; o >>= 1) {
            pi += __shfl_xor_sync(0xffffffffu, pi, o);
            pj += __shfl_xor_sync(0xffffffffu, pj, o);
        }
        if (lane == 0) { g_si[i] = pi; g_sj[i] = pj; }
    }
}

// ---------------------------------------------------------------------------
// Kernel B (HBM-bound, PROTECTED WIN): per row i, fused dual GEMV +
// leaky-ReLU + mask + softmax (unnormalized store + g_inv).
// __launch_bounds__(256,7) -> 7 blocks/SM -> ALL 1024 blocks in ONE wave.
// ---------------------------------------------------------------------------
__global__ __launch_bounds__(256, 7) void k_attn(const float* __restrict__ eh,
                                                 const float* __restrict__ de,
                                                 const int* __restrict__ adj,
                                                 const float* __restrict__ aw,
                                                 const float* __restrict__ ab) {
    int i = blockIdx.x;
    int tid = threadIdx.x;
    int warp = tid >> 5, lane = tid & 31;

    __shared__ float sh[NN];
    __shared__ float red[8];

    float4 ae = ((const float4*)(aw + 2 * FF))[lane];
    float4 ad = ((const float4*)(aw + 3 * FF))[lane];
    float base = g_si[i] + ab[0];

    const float4* pe = (const float4*)(eh + (size_t)i * NN * FF);
    const float4* pd = (const float4*)(de + (size_t)i * NN * FF);

    // Stream 1 MB (e_h row-block + dialogue row-block); fused dual dot.
#pragma unroll 2
    for (int j = warp; j < NN; j += 8) {
        float4 x = ldcs4(pe + j * 32 + lane);
        float4 y = ldcs4(pd + j * 32 + lane);
        float p = fmaf(x.x, ae.x, fmaf(x.y, ae.y, fmaf(x.z, ae.z, x.w * ae.w)));
        p = fmaf(y.x, ad.x, fmaf(y.y, ad.y, fmaf(y.z, ad.z, fmaf(y.w, ad.w, p))));
#pragma unroll
        for (int o = 16; o; o >>= 1) p += __shfl_xor_sync(0xffffffffu, p, o);
        if (lane == 0) {
            float v = base + g_sj[j] + p;
            sh[j] = v > 0.f ? v : ALPHA * v;
        }
    }
    __syncthreads();

    // Mask + max: each thread owns exactly 4 j's (stay in registers after).
    int4 a4 = ((const int4*)(adj + (size_t)i * NN))[tid];
    float4 v4 = *((float4*)&sh[tid * 4]);
    v4.x = a4.x > 0 ? v4.x : NEGV;
    v4.y = a4.y > 0 ? v4.y : NEGV;
    v4.z = a4.z > 0 ? v4.z : NEGV;
    v4.w = a4.w > 0 ? v4.w : NEGV;
    float m = fmaxf(fmaxf(v4.x, v4.y), fmaxf(v4.z, v4.w));
#pragma unroll
    for (int o = 16; o; o >>= 1) m = fmaxf(m, __shfl_xor_sync(0xffffffffu, m, o));
    if (lane == 0) red[warp] = m;
    __syncthreads();
    float mm = red[0];
#pragma unroll
    for (int k = 1; k < 8; k++) mm = fmaxf(mm, red[k]);

    // exp + sum; store UNNORMALIZED weights; inv goes to g_inv.
    float4 e4;
    e4.x = __expf(v4.x - mm);
    e4.y = __expf(v4.y - mm);
    e4.z = __expf(v4.z - mm);
    e4.w = __expf(v4.w - mm);
    ((float4*)(g_att + (size_t)i * NN))[tid] = e4;
    float s = (e4.x + e4.y) + (e4.z + e4.w);
#pragma unroll
    for (int o = 16; o; o >>= 1) s += __shfl_xor_sync(0xffffffffu, s, o);
    __syncthreads();              // red[] (max) fully consumed before reuse
    if (lane == 0) red[warp] = s;
    __syncthreads();
    if (tid == 0) {
        float tot = red[0];
#pragma unroll
        for (int k = 1; k < 8; k++) tot += red[k];
        g_inv[i] = 1.f / tot;
    }
}

// ---------------------------------------------------------------------------
// Kernel D (PROTECTED): out = elu((att*inv) @ Wh).  256 blocks x 256, 4 rows.
// Attention rows staged TRANSPOSED in smem (inv folded in), inner loop =
// 1 broadcast LDS.128 + 1 coalesced LDG.128 + 16 FMA per j.
// ---------------------------------------------------------------------------
__global__ __launch_bounds__(256) void k_out(float* __restrict__ out) {
    int tid = threadIdx.x;
    int warp = tid >> 5, lane = tid & 31;
    int i0 = blockIdx.x * 4;

    __shared__ float4 attT[NN];        // attT[j] = {row0..row3} * inv  (16 KB)
    __shared__ float4 sred[4][8][32];  // cross-warp reduce              (16 KB)

    float iv0 = g_inv[i0 + 0], iv1 = g_inv[i0 + 1];
    float iv2 = g_inv[i0 + 2], iv3 = g_inv[i0 + 3];
    const float* att0 = g_att + (size_t)(i0 + 0) * NN;
    const float* att1 = g_att + (size_t)(i0 + 1) * NN;
    const float* att2 = g_att + (size_t)(i0 + 2) * NN;
    const float* att3 = g_att + (size_t)(i0 + 3) * NN;
#pragma unroll
    for (int q = 0; q < 4; q++) {
        int j = tid + q * 256;
        float4 v;
        v.x = att0[j] * iv0;
        v.y = att1[j] * iv1;
        v.z = att2[j] * iv2;
        v.w = att3[j] * iv3;
        attT[j] = v;                   // STS.128, lanes consecutive -> no conflict
    }
    __syncthreads();

    float4 c0 = make_float4(0.f, 0.f, 0.f, 0.f);
    float4 c1 = c0, c2 = c0, c3 = c0;
    const float4* wh4 = (const float4*)g_Wh;
    int jb = warp * 128;
#pragma unroll 4
    for (int jj = 0; jj < 128; jj++) {
        float4 a = attT[jb + jj];                       // broadcast
        float4 w = wh4[(size_t)(jb + jj) * 32 + lane];  // coalesced 512B/warp
        c0.x = fmaf(a.x, w.x, c0.x); c0.y = fmaf(a.x, w.y, c0.y);
        c0.z = fmaf(a.x, w.z, c0.z); c0.w = fmaf(a.x, w.w, c0.w);
        c1.x = fmaf(a.y, w.x, c1.x); c1.y = fmaf(a.y, w.y, c1.y);
        c1.z = fmaf(a.y, w.z, c1.z); c1.w = fmaf(a.y, w.w, c1.w);
        c2.x = fmaf(a.z, w.x, c2.x); c2.y = fmaf(a.z, w.y, c2.y);
        c2.z = fmaf(a.z, w.z, c2.z); c2.w = fmaf(a.z, w.w, c2.w);
        c3.x = fmaf(a.w, w.x, c3.x); c3.y = fmaf(a.w, w.y, c3.y);
        c3.z = fmaf(a.w, w.z, c3.z); c3.w = fmaf(a.w, w.w, c3.w);
    }
    sred[0][warp][lane] = c0;
    sred[1][warp][lane] = c1;
    sred[2][warp][lane] = c2;
    sred[3][warp][lane] = c3;
    __syncthreads();

    if (tid < 128) {
        int r = tid >> 5, c = tid & 31;
        float4 s = sred[r][0][c];
#pragma unroll
        for (int w = 1; w < 8; w++) {
            float4 o = sred[r][w][c];
            s.x += o.x; s.y += o.y; s.z += o.z; s.w += o.w;
        }
        float4 res;
        res.x = s.x > 0.f ? s.x : expm1f(s.x);
        res.y = s.y > 0.f ? s.y : expm1f(s.y);
        res.z = s.z > 0.f ? s.z : expm1f(s.z);
        res.w = s.w > 0.f ? s.w : expm1f(s.w);
        ((float4*)(out + (size_t)(i0 + r) * FF))[c] = res;
    }
}

// ---------------------------------------------------------------------------
// Launch.  Inputs: h, e_h, dialogue_embedding, adj, W_w, W_b, a_w, a_b.
// Output: fp32 [1024, 128].
// ---------------------------------------------------------------------------
extern "C" void kernel_launch(void* const* d_in, const int* in_sizes, int n_in,
                              void* d_out, int out_size) {
    const float* h   = (const float*)d_in[0];
    const float* eh  = (const float*)d_in[1];
    const float* de  = (const float*)d_in[2];
    const int*   adj = (const int*)d_in[3];
    const float* Ww  = (const float*)d_in[4];
    const float* Wb  = (const float*)d_in[5];
    const float* aw  = (const float*)d_in[6];
    const float* ab  = (const float*)d_in[7];
    float* out = (float*)d_out;

    k_wh<<<NN, 128>>>(h, Ww, Wb, aw);
    k_attn<<<NN, 256>>>(eh, de, adj, aw, ab);
    k_out<<<NN / 4, 256>>>(out);
}